// round 9
// baseline (speedup 1.0000x reference)
#include <cuda_runtime.h>
#include <cuda_bf16.h>

typedef unsigned long long ull;
typedef unsigned u32;

#define DD 96
#define HH 320
#define WW 320
#define NVOX (DD*HH*WW)
#define CIN 64
#define COUT 64
#define EPSV 1e-5f
#define SLOPE 0.01f
#define RSLOTS 4096

__device__ int   g_grid[NVOX];          // coord -> row+1, 0 = empty
__device__ float g_stats[2 * COUT];
__device__ int   g_cnt[27];
__device__ int2  g_rule[27][RSLOTS];
// Pre-split, pre-transposed weights: WT[k][co][ci] as bf16 hi/lo (ull = 4 bf16).
__device__ ull   g_wt_hi[27][1024];
__device__ ull   g_wt_lo[27][1024];

// ---------------- helpers ----------------
static __device__ __forceinline__ unsigned pack_bf(float a, float b) {
    __nv_bfloat16 ha = __float2bfloat16(a), hb = __float2bfloat16(b);
    unsigned short ua = *(unsigned short*)&ha, ub = *(unsigned short*)&hb;
    return (unsigned)ua | ((unsigned)ub << 16);
}
static __device__ __forceinline__ void split2(float a, float b,
                                              u32& hi, u32& lo)
{
    __nv_bfloat16 ha = __float2bfloat16(a), hb = __float2bfloat16(b);
    float ra = a - __bfloat162float(ha);
    float rb = b - __bfloat162float(hb);
    hi = pack_bf(a, b);
    lo = pack_bf(ra, rb);
}
static __device__ __forceinline__ void mma16816(
    float* c, u32 a0, u32 a1, u32 a2, u32 a3, u32 b0, u32 b1)
{
    asm volatile(
        "mma.sync.aligned.m16n8k16.row.col.f32.bf16.bf16.f32 "
        "{%0,%1,%2,%3}, {%4,%5,%6,%7}, {%8,%9}, {%0,%1,%2,%3};"
        : "+f"(c[0]), "+f"(c[1]), "+f"(c[2]), "+f"(c[3])
        : "r"(a0), "r"(a1), "r"(a2), "r"(a3), "r"(b0), "r"(b1));
}
static __device__ __forceinline__ void ldsm4(
    u32& r0, u32& r1, u32& r2, u32& r3, u32 addr)
{
    asm volatile(
        "ldmatrix.sync.aligned.m8n8.x4.shared.b16 {%0,%1,%2,%3}, [%4];"
        : "=r"(r0), "=r"(r1), "=r"(r2), "=r"(r3) : "r"(addr));
}
// rotation swizzle: u32 column within a 32-u32 row, rotated by 4*row.
// Keeps aligned 4-u32 chunks contiguous (rotation is a multiple of 4 when
// applied to aligned chunks), so 16B ldmatrix rows never split.
#define ROT(row, col) (((row) << 5) + (((col) + ((row) << 2)) & 31))

// ---------------- bookkeeping kernels ----------------
__global__ void scatter_kernel(const int* __restrict__ coords, int n) {
    int i = blockIdx.x * blockDim.x + threadIdx.x;
    if (i < 2 * COUT) g_stats[i] = 0.0f;
    if (i < 27) g_cnt[i] = 0;
    if (i >= n) return;
    int z = coords[3 * i + 0];
    int y = coords[3 * i + 1];
    int x = coords[3 * i + 2];
    g_grid[(z * HH + y) * WW + x] = i + 1;
}

__global__ void __launch_bounds__(256) wsplit_kernel(const float* __restrict__ wgt) {
    int idx = blockIdx.x * blockDim.x + threadIdx.x;   // [k][co][ci]
    if (idx >= 27 * 4096) return;
    int k  = idx >> 12;
    int e  = idx & 4095;
    int co = e >> 6;
    int ci = e & 63;
    float w = wgt[(k * 64 + ci) * 64 + co];
    __nv_bfloat16 h = __float2bfloat16(w);
    float r = w - __bfloat162float(h);
    __nv_bfloat16 l = __float2bfloat16(r);
    ((__nv_bfloat16*)g_wt_hi)[idx] = h;
    ((__nv_bfloat16*)g_wt_lo)[idx] = l;
}

__global__ void __launch_bounds__(256) rulebook_kernel(
    const int* __restrict__ coords, int n)
{
    int t = blockIdx.x * blockDim.x + threadIdx.x;
    if (t >= n * 13) return;
    int v = t / 13;
    int k = t - v * 13;

    int z = coords[3 * v + 0] + k / 9       - 1;
    int y = coords[3 * v + 1] + (k / 3) % 3 - 1;
    int x = coords[3 * v + 2] + k % 3       - 1;
    if (z < 0 || z >= DD || y < 0 || y >= HH || x < 0 || x >= WW) return;
    int val = g_grid[(z * HH + y) * WW + x];
    if (val == 0) return;
    int j = val - 1;

    int p0 = atomicAdd(&g_cnt[k], 1);
    if (p0 < RSLOTS) g_rule[k][p0] = make_int2(v, j);
    int p1 = atomicAdd(&g_cnt[26 - k], 1);
    if (p1 < RSLOTS) g_rule[26 - k][p1] = make_int2(j, v);
}

// ---------------------------------------------------------------------------
// MMA core. SMEM 48 KB. A: 128x32 u32 (bf16 pairs along ci), rotation-
// swizzled, hi+lo. B: 64x32 u32, rotation-swizzled, hi+lo.
// 8 warps, warp w owns rows w*16..+15. Fragments via ldmatrix.x4.
// 3 passes: Ah*Bh, Al*Bh, Ah*Bl, fp32 accumulators persistent.
// ---------------------------------------------------------------------------
struct MmaSmem {
    u32 Ahi[128 * 32];
    u32 Alo[128 * 32];
    u32 Bhi[64 * 32];
    u32 Blo[64 * 32];
};

static __device__ __forceinline__ void stage_B(
    MmaSmem& s, const ull* __restrict__ wh, const ull* __restrict__ wl, int tid)
{
    #pragma unroll
    for (int t = 0; t < 4; t++) {
        int e  = tid + t * 256;      // 1024 ull entries
        int co = e >> 4;
        int j  = e & 15;             // u32 cols 2j, 2j+1
        ull vh = wh[e];
        ull vl = wl[e];
        s.Bhi[ROT(co, 2 * j    )] = (u32)vh;
        s.Bhi[ROT(co, 2 * j + 1)] = (u32)(vh >> 32);
        s.Blo[ROT(co, 2 * j    )] = (u32)vl;
        s.Blo[ROT(co, 2 * j + 1)] = (u32)(vl >> 32);
    }
}

static __device__ __forceinline__ void mma_passes(
    const MmaSmem& s, float acc[8][4], int m0, int lane)
{
    const u32 sAhi = (u32)__cvta_generic_to_shared(s.Ahi);
    const u32 sAlo = (u32)__cvta_generic_to_shared(s.Alo);
    const u32 sBhi = (u32)__cvta_generic_to_shared(s.Bhi);
    const u32 sBlo = (u32)__cvta_generic_to_shared(s.Blo);

    const int sub = lane >> 3;
    const int l7  = lane & 7;
    // A: matrices (rows 0-7,k0),(rows 8-15,k0),(rows 0-7,k16B),(rows 8-15,k16B)
    const int rowA = m0 + l7 + ((sub & 1) << 3);
    const int cqA  = (sub >> 1) << 2;
    // B: matrices (n 0-7,k0),(n 0-7,k16B),(n 8-15,k0),(n 8-15,k16B)
    const int rowB = ((sub >> 1) << 3) + l7;     // + nfp*16
    const int cqB  = (sub & 1) << 2;

    const u32 Ab[3] = { sAhi, sAlo, sAhi };
    const u32 Bb[3] = { sBhi, sBhi, sBlo };

    #pragma unroll
    for (int pass = 0; pass < 3; pass++) {
        #pragma unroll
        for (int kf = 0; kf < 4; kf++) {
            u32 a0, a1, a2, a3;
            u32 ca = (u32)((kf * 8 + cqA + (rowA << 2)) & 31);
            ldsm4(a0, a1, a2, a3, Ab[pass] + 4u * ((u32)(rowA << 5) + ca));
            #pragma unroll
            for (int nfp = 0; nfp < 4; nfp++) {
                int rb = nfp * 16 + rowB;
                u32 cb = (u32)((kf * 8 + cqB + (rb << 2)) & 31);
                u32 b0, b1, b2, b3;
                ldsm4(b0, b1, b2, b3, Bb[pass] + 4u * ((u32)(rb << 5) + cb));
                mma16816(acc[2 * nfp],     a0, a1, a2, a3, b0, b1);
                mma16816(acc[2 * nfp + 1], a0, a1, a2, a3, b2, b3);
            }
        }
    }
}

// ---------------------------------------------------------------------------
// Center tap: out[128 rows] = feat @ W13.
// ---------------------------------------------------------------------------
__global__ void __launch_bounds__(256) center_mma_kernel(
    const float* __restrict__ feat, float* __restrict__ out, int n)
{
    __shared__ MmaSmem s;
    const int tid   = threadIdx.x;
    const int rbase = blockIdx.x * 128;

    #pragma unroll
    for (int t = 0; t < 8; t++) {
        int e  = tid + t * 256;      // 2048 float4
        int r  = e >> 4;
        int q  = e & 15;
        int gr = rbase + r;
        float4 v = (gr < n) ? *(const float4*)&feat[(size_t)gr * CIN + q * 4]
                            : make_float4(0.f, 0.f, 0.f, 0.f);
        u32 h0, l0, h1, l1;
        split2(v.x, v.y, h0, l0);
        split2(v.z, v.w, h1, l1);
        s.Ahi[ROT(r, 2 * q    )] = h0;
        s.Ahi[ROT(r, 2 * q + 1)] = h1;
        s.Alo[ROT(r, 2 * q    )] = l0;
        s.Alo[ROT(r, 2 * q + 1)] = l1;
    }
    stage_B(s, g_wt_hi[13], g_wt_lo[13], tid);
    __syncthreads();

    const int wid  = tid >> 5;
    const int lane = tid & 31;
    const int g    = lane >> 2;
    const int tig  = lane & 3;
    const int m0   = wid * 16;

    float acc[8][4];
    #pragma unroll
    for (int nf = 0; nf < 8; nf++)
        acc[nf][0] = acc[nf][1] = acc[nf][2] = acc[nf][3] = 0.f;

    mma_passes(s, acc, m0, lane);

    int row0 = rbase + m0 + g;
    int row1 = row0 + 8;
    #pragma unroll
    for (int nf = 0; nf < 8; nf++) {
        int c = nf * 8 + tig * 2;
        if (row0 < n) *(float2*)&out[(size_t)row0 * COUT + c] =
            make_float2(acc[nf][0], acc[nf][1]);
        if (row1 < n) *(float2*)&out[(size_t)row1 * COUT + c] =
            make_float2(acc[nf][2], acc[nf][3]);
    }
}

// ---------------------------------------------------------------------------
// Tap GEMM: 128 rulebook pairs of ONE tap, atomicAdd scatter.
// ---------------------------------------------------------------------------
__global__ void __launch_bounds__(256) tap_mma_kernel(
    const float* __restrict__ feat, float* __restrict__ out)
{
    const int ky = blockIdx.y;
    int cnt = g_cnt[ky];
    if (cnt > RSLOTS) cnt = RSLOTS;
    const int base = blockIdx.x * 128;
    if (base >= cnt) return;

    __shared__ MmaSmem s;
    const int tid = threadIdx.x;
    const int2* rule = g_rule[ky];

    #pragma unroll
    for (int t = 0; t < 8; t++) {
        int e = tid + t * 256;
        int r = e >> 4;
        int q = e & 15;
        int j = (base + r < cnt) ? rule[base + r].y : -1;
        float4 v = (j >= 0) ? *(const float4*)&feat[(size_t)j * CIN + q * 4]
                            : make_float4(0.f, 0.f, 0.f, 0.f);
        u32 h0, l0, h1, l1;
        split2(v.x, v.y, h0, l0);
        split2(v.z, v.w, h1, l1);
        s.Ahi[ROT(r, 2 * q    )] = h0;
        s.Ahi[ROT(r, 2 * q + 1)] = h1;
        s.Alo[ROT(r, 2 * q    )] = l0;
        s.Alo[ROT(r, 2 * q + 1)] = l1;
    }
    stage_B(s, g_wt_hi[ky], g_wt_lo[ky], tid);
    __syncthreads();

    const int wid  = tid >> 5;
    const int lane = tid & 31;
    const int g    = lane >> 2;
    const int tig  = lane & 3;
    const int m0   = wid * 16;

    float acc[8][4];
    #pragma unroll
    for (int nf = 0; nf < 8; nf++)
        acc[nf][0] = acc[nf][1] = acc[nf][2] = acc[nf][3] = 0.f;

    mma_passes(s, acc, m0, lane);

    int i0 = (base + m0 + g     < cnt) ? rule[base + m0 + g].x     : -1;
    int i1 = (base + m0 + g + 8 < cnt) ? rule[base + m0 + g + 8].x : -1;
    #pragma unroll
    for (int nf = 0; nf < 8; nf++) {
        int c = nf * 8 + tig * 2;
        if (i0 >= 0) {
            float* ob = out + (size_t)i0 * COUT + c;
            atomicAdd(ob + 0, acc[nf][0]);
            atomicAdd(ob + 1, acc[nf][1]);
        }
        if (i1 >= 0) {
            float* ob = out + (size_t)i1 * COUT + c;
            atomicAdd(ob + 0, acc[nf][2]);
            atomicAdd(ob + 1, acc[nf][3]);
        }
    }
}

// ---------------- BN stats reduce + grid clear (merged) ----------------
#define RED_BLOCKS 592

__global__ void __launch_bounds__(256) reduce_clear_kernel(
    const float* __restrict__ out, const int* __restrict__ coords, int n)
{
    if (blockIdx.x >= RED_BLOCKS) {
        int i = (blockIdx.x - RED_BLOCKS) * 256 + threadIdx.x;
        if (i < n) {
            int z = coords[3 * i + 0];
            int y = coords[3 * i + 1];
            int x = coords[3 * i + 2];
            g_grid[(z * HH + y) * WW + x] = 0;
        }
        return;
    }

    const int tid = threadIdx.x;
    const int c4  = (tid & 15) << 2;
    const int rg  = tid >> 4;

    float4 sv = make_float4(0.f, 0.f, 0.f, 0.f);
    float4 qv = make_float4(0.f, 0.f, 0.f, 0.f);

    for (int row = blockIdx.x * 16 + rg; row < n; row += RED_BLOCKS * 16) {
        float4 v = *(const float4*)&out[(size_t)row * COUT + c4];
        sv.x += v.x; sv.y += v.y; sv.z += v.z; sv.w += v.w;
        qv.x += v.x * v.x; qv.y += v.y * v.y;
        qv.z += v.z * v.z; qv.w += v.w * v.w;
    }

    sv.x += __shfl_xor_sync(0xffffffffu, sv.x, 16);
    sv.y += __shfl_xor_sync(0xffffffffu, sv.y, 16);
    sv.z += __shfl_xor_sync(0xffffffffu, sv.z, 16);
    sv.w += __shfl_xor_sync(0xffffffffu, sv.w, 16);
    qv.x += __shfl_xor_sync(0xffffffffu, qv.x, 16);
    qv.y += __shfl_xor_sync(0xffffffffu, qv.y, 16);
    qv.z += __shfl_xor_sync(0xffffffffu, qv.z, 16);
    qv.w += __shfl_xor_sync(0xffffffffu, qv.w, 16);

    __shared__ float wred[2][8][COUT];
    const int w = tid >> 5;
    if ((tid & 31) < 16) {
        *(float4*)&wred[0][w][c4] = sv;
        *(float4*)&wred[1][w][c4] = qv;
    }
    __syncthreads();

    if (tid < 2 * COUT) {
        int half = tid >> 6;
        int c    = tid & 63;
        float acc = 0.f;
        #pragma unroll
        for (int ww = 0; ww < 8; ww++) acc += wred[half][ww][c];
        atomicAdd(&g_stats[tid], acc);
    }
}

__global__ void __launch_bounds__(256) bn_kernel(
    float4* __restrict__ out, const float* __restrict__ gamma,
    const float* __restrict__ beta, int n4, float invN)
{
    __shared__ float ssc[COUT], sbi[COUT];
    if (threadIdx.x < COUT) {
        float mean = g_stats[threadIdx.x] * invN;
        float var  = g_stats[COUT + threadIdx.x] * invN - mean * mean;
        float sc   = gamma[threadIdx.x] * rsqrtf(var + EPSV);
        ssc[threadIdx.x] = sc;
        sbi[threadIdx.x] = beta[threadIdx.x] - mean * sc;
    }
    __syncthreads();

    int idx = blockIdx.x * blockDim.x + threadIdx.x;
    if (idx >= n4) return;
    int c4 = (idx & 15) << 2;

    float4 vv = out[idx];
    float r;
    r = vv.x * ssc[c4 + 0] + sbi[c4 + 0]; vv.x = (r >= 0.f) ? r : SLOPE * r;
    r = vv.y * ssc[c4 + 1] + sbi[c4 + 1]; vv.y = (r >= 0.f) ? r : SLOPE * r;
    r = vv.z * ssc[c4 + 2] + sbi[c4 + 2]; vv.z = (r >= 0.f) ? r : SLOPE * r;
    r = vv.w * ssc[c4 + 3] + sbi[c4 + 3]; vv.w = (r >= 0.f) ? r : SLOPE * r;
    out[idx] = vv;
}

extern "C" void kernel_launch(void* const* d_in, const int* in_sizes, int n_in,
                              void* d_out, int out_size)
{
    const float* feat   = (const float*)d_in[0];
    const int*   coords = (const int*)  d_in[1];
    const float* wgt    = (const float*)d_in[2];
    const float* gamma  = (const float*)d_in[3];
    const float* beta   = (const float*)d_in[4];
    float*       out    = (float*)d_out;

    const int n = in_sizes[0] / CIN;

    scatter_kernel<<<(n + 255) / 256, 256>>>(coords, n);
    wsplit_kernel<<<(27 * 4096 + 255) / 256, 256>>>(wgt);
    rulebook_kernel<<<(n * 13 + 255) / 256, 256>>>(coords, n);
    center_mma_kernel<<<(n + 127) / 128, 256>>>(feat, out, n);
    {
        dim3 grid(RSLOTS / 128, 27);
        tap_mma_kernel<<<grid, 256>>>(feat, out);
    }
    reduce_clear_kernel<<<RED_BLOCKS + (n + 255) / 256, 256>>>(out, coords, n);
    bn_kernel<<<(n * (COUT / 4) + 255) / 256, 256>>>(
        (float4*)out, gamma, beta, n * (COUT / 4), 1.0f / (float)n);
}